// round 15
// baseline (speedup 1.0000x reference)
#include <cuda_runtime.h>
#include <cuda_fp16.h>
#include <cstdint>

// Block-diagonal linear: y[n, b*64+j] = sum_{k<64} x[n, b*64+k] * w[b*64+j, b*64+k]
// R15: R14 core (pure fp16 m16n8k16, ldmatrix A, reg-pinned B, line-minimized
// global access) + distance-2 prefetch (3-buffer X ring: LDG issued one full tile
// before its STS) + single barrier per tile (double-buffered C staging).
// rel_err ~2.9e-4 (tolerance 1e-3).

#define N_FEAT   4096
#define BLK      64
#define NBLK     64
#define TROWS    64
#define MULTI    4
#define THREADS  256
#define XSP      36                 // u32 stride X/W planes (ldmatrix conflict-free)
#define PLANE    (TROWS * XSP)      // 2304 u32 per X buffer
#define CSP      68                 // f32 stride of C smem tile (LDS.128 conflict-free)

// dynamic smem layout (bytes)
#define SX_OFF   0
#define SX_BYTES (3 * PLANE * 4)                 // 27648
#define SW_OFF   (SX_OFF + SX_BYTES)             // 27648
#define SW_BYTES (PLANE * 4)                     // 9216
#define SC_OFF   (SW_OFF + SW_BYTES)             // 36864
#define SC_BYTES (2 * TROWS * CSP * 4)           // 34816
#define SMEM_B   (SC_OFF + SC_BYTES)             // 71680

__device__ __forceinline__ uint32_t pack_h2(float a, float b) {
    __half2 H = __float22half2_rn(make_float2(a, b));
    return *(uint32_t*)&H;
}

__device__ __forceinline__ void mma16816(float c[4],
                                         uint32_t a0, uint32_t a1, uint32_t a2, uint32_t a3,
                                         uint32_t b0, uint32_t b1) {
    asm volatile(
        "mma.sync.aligned.m16n8k16.row.col.f32.f16.f16.f32 "
        "{%0,%1,%2,%3}, {%4,%5,%6,%7}, {%8,%9}, {%0,%1,%2,%3};"
        : "+f"(c[0]), "+f"(c[1]), "+f"(c[2]), "+f"(c[3])
        : "r"(a0), "r"(a1), "r"(a2), "r"(a3), "r"(b0), "r"(b1));
}

__device__ __forceinline__ void ldm_x4(uint32_t& r0, uint32_t& r1, uint32_t& r2, uint32_t& r3,
                                       uint32_t addr) {
    asm volatile("ldmatrix.sync.aligned.m8n8.x4.shared.b16 {%0,%1,%2,%3}, [%4];"
                 : "=r"(r0), "=r"(r1), "=r"(r2), "=r"(r3) : "r"(addr));
}

__global__ __launch_bounds__(THREADS, 3)
void sl_blockdiag_kernel(const float* __restrict__ x,
                         const float* __restrict__ w,
                         float* __restrict__ out) {
    extern __shared__ __align__(16) char dsm[];
    uint32_t* sXg = (uint32_t*)(dsm + SX_OFF);   // 3 X buffers
    uint32_t* sWp = (uint32_t*)(dsm + SW_OFF);   // W plane
    float*    sC  = (float*)(dsm + SC_OFF);      // 2 C tiles

    const int b  = blockIdx.x % NBLK;
    const int tg = blockIdx.x / NBLK;
    const int tid = threadIdx.x;
    const size_t colbase = (size_t)b * BLK;
    const size_t row0cta = (size_t)tg * (TROWS * MULTI);

    // staging coords: warp = 2 rows x 16 float4-chunks (4 lines per LDG/STG.128)
    const int xr = tid >> 4;        // base row 0..15
    const int xq = tid & 15;        // float4 chunk within row

    // ---- stage W_b (fp16 round, packed pairs) ----
    #pragma unroll
    for (int i = tid; i < BLK * 16; i += THREADS) {
        int r = i >> 4, q = i & 15;
        float4 v = *(const float4*)(w + (colbase + r) * N_FEAT + colbase + q * 4);
        sWp[r * XSP + 2 * q]     = pack_h2(v.x, v.y);
        sWp[r * XSP + 2 * q + 1] = pack_h2(v.z, v.w);
    }

    // ---- stage X tile 0 into buffer 0; LDG tile 1 into registers ----
    float4 p[4];
    {
        const float* base0 = x + row0cta * N_FEAT + colbase + 4 * xq;
        #pragma unroll
        for (int j = 0; j < 4; j++) {
            int r = xr + 16 * j;
            float4 v = *(const float4*)(base0 + (size_t)r * N_FEAT);
            uint32_t* d = &sXg[r * XSP + 2 * xq];
            d[0] = pack_h2(v.x, v.y);
            d[1] = pack_h2(v.z, v.w);
        }
        const float* base1 = base0 + (size_t)TROWS * N_FEAT;
        #pragma unroll
        for (int j = 0; j < 4; j++)
            p[j] = *(const float4*)(base1 + (size_t)(xr + 16 * j) * N_FEAT);
    }
    __syncthreads();

    const int wid  = tid >> 5;
    const int lane = tid & 31;
    const int g    = lane >> 2;
    const int tq   = lane & 3;
    const int mg   = wid >> 1;
    const int nh   = wid & 1;
    const int m0   = mg * 16;

    // ---- B fragments -> registers (CTA lifetime) ----
    uint32_t bh[4][4][2];
    #pragma unroll
    for (int nt = 0; nt < 4; nt++) {
        int nrow = (nh * 4 + nt) * 8 + g;
        #pragma unroll
        for (int ks = 0; ks < 4; ks++) {
            int a = nrow * XSP + ks * 8 + tq;
            bh[nt][ks][0] = sWp[a];
            bh[nt][ks][1] = sWp[a + 4];
        }
    }

    // ldmatrix address precompute
    const int lane7 = lane & 7;
    const int mat   = lane >> 3;
    const int arow  = m0 + lane7 + ((mat & 1) << 3);
    const int acolu = (mat >> 1) << 2;
    const uint32_t aoff = (uint32_t)(arow * XSP + acolu) * 4u;
    const uint32_t sb0  = (uint32_t)__cvta_generic_to_shared(sXg);
    const uint32_t bufbytes = (uint32_t)PLANE * 4u;

    #pragma unroll
    for (int t = 0; t < MULTI; t++) {
        // (1) STS registers loaded last tile -> buffer (t+1)%3
        if (t + 1 < MULTI) {
            uint32_t* nb = sXg + ((t + 1) % 3) * PLANE;
            #pragma unroll
            for (int j = 0; j < 4; j++) {
                uint32_t* d = &nb[(xr + 16 * j) * XSP + 2 * xq];
                d[0] = pack_h2(p[j].x, p[j].y);
                d[1] = pack_h2(p[j].z, p[j].w);
            }
        }
        // (2) LDG tile t+2 -> registers (full tile of slack before its STS)
        if (t + 2 < MULTI) {
            const float* base = x + (row0cta + (size_t)(t + 2) * TROWS) * N_FEAT + colbase + 4 * xq;
            #pragma unroll
            for (int j = 0; j < 4; j++)
                p[j] = *(const float4*)(base + (size_t)(xr + 16 * j) * N_FEAT);
        }

        // (3) MMA from buffer t%3
        const uint32_t tb = sb0 + (uint32_t)(t % 3) * bufbytes;
        float c[4][4];
        #pragma unroll
        for (int i = 0; i < 4; i++)
            #pragma unroll
            for (int j = 0; j < 4; j++) c[i][j] = 0.f;

        #pragma unroll
        for (int ks = 0; ks < 4; ks++) {
            uint32_t a0, a1, a2, a3;
            ldm_x4(a0, a1, a2, a3, tb + aoff + (uint32_t)(ks * 8) * 4u);
            #pragma unroll
            for (int nt = 0; nt < 4; nt++)
                mma16816(c[nt], a0, a1, a2, a3, bh[nt][ks][0], bh[nt][ks][1]);
        }

        // (4) STS C fragments -> sC[t&1]
        float* ct = sC + (t & 1) * (TROWS * CSP);
        {
            const int r0 = m0 + g;
            #pragma unroll
            for (int nt = 0; nt < 4; nt++) {
                int col = nh * 32 + nt * 8 + tq * 2;
                *(float2*)(ct + r0 * CSP + col)       = make_float2(c[nt][0], c[nt][1]);
                *(float2*)(ct + (r0 + 8) * CSP + col) = make_float2(c[nt][2], c[nt][3]);
            }
        }

        // (5) single barrier per tile
        __syncthreads();

        // (6) coalesced STG from sC[t&1]
        {
            const size_t rowbase = row0cta + (size_t)t * TROWS;
            float* obase = out + rowbase * N_FEAT + colbase + 4 * xq;
            #pragma unroll
            for (int j = 0; j < 4; j++) {
                int r = xr + 16 * j;
                float4 v = *(const float4*)(ct + r * CSP + 4 * xq);
                *(float4*)(obase + (size_t)r * N_FEAT) = v;
            }
        }
    }
}

extern "C" void kernel_launch(void* const* d_in, const int* in_sizes, int n_in,
                              void* d_out, int out_size) {
    const float* x = (const float*)d_in[0];
    const float* w = (const float*)d_in[1];
    float* out = (float*)d_out;

    const int n_rows = in_sizes[0] / N_FEAT;                 // 8192
    const int tile_groups = n_rows / (TROWS * MULTI);        // 32

    cudaFuncSetAttribute(sl_blockdiag_kernel,
                         cudaFuncAttributeMaxDynamicSharedMemorySize, SMEM_B);

    dim3 grid(NBLK * tile_groups);                           // 2048 CTAs
    sl_blockdiag_kernel<<<grid, THREADS, SMEM_B>>>(x, w, out);
}